// round 17
// baseline (speedup 1.0000x reference)
#include <cuda_runtime.h>
#include <cuda_bf16.h>
#include <mma.h>
#include <cstdint>

using namespace nvcuda;

// ---------------- problem constants ----------------
#define BATCH 4
#define SEQ 8192
#define DM 1024
#define NH 16
#define HD 64
#define NCHUNK 32
#define MTOT (BATCH * SEQ) // 32768

// ---------------- scratch (device globals; no allocs) ----------------
__device__ __nv_bfloat16 g_qh[MTOT * DM];
__device__ __nv_bfloat16 g_ql[MTOT * DM];
__device__ __nv_bfloat16 g_kh[MTOT * DM];
__device__ __nv_bfloat16 g_kl[MTOT * DM];
__device__ __nv_bfloat16 g_vh[MTOT * DM];
__device__ __nv_bfloat16 g_vl[MTOT * DM];
__device__ __nv_bfloat16 g_ah[MTOT * DM]; // hi split of x, later of attn-out
__device__ __nv_bfloat16 g_al[MTOT * DM]; // lo split
__device__ __nv_bfloat16 g_wh[4 * DM * DM]; // transposed weights hi (q,k,v,o)
__device__ __nv_bfloat16 g_wl[4 * DM * DM]; // transposed weights lo

__device__ __forceinline__ void split1(float x, __nv_bfloat16& h, __nv_bfloat16& l) {
    h = __float2bfloat16_rn(x);
    l = __float2bfloat16_rn(x - __bfloat162float(h));
}

// pack 4 floats into hi-uint2 and lo-uint2 (4 bf16 each)
__device__ __forceinline__ void split4_pack(const float* f, uint2& hp, uint2& lp) {
    __nv_bfloat16 h0, h1, h2, h3, l0, l1, l2, l3;
    split1(f[0], h0, l0); split1(f[1], h1, l1);
    split1(f[2], h2, l2); split1(f[3], h3, l3);
    __nv_bfloat162 ha; ha.x = h0; ha.y = h1;
    __nv_bfloat162 hb; hb.x = h2; hb.y = h3;
    __nv_bfloat162 la; la.x = l0; la.y = l1;
    __nv_bfloat162 lb; lb.x = l2; lb.y = l3;
    hp.x = *reinterpret_cast<uint32_t*>(&ha);
    hp.y = *reinterpret_cast<uint32_t*>(&hb);
    lp.x = *reinterpret_cast<uint32_t*>(&la);
    lp.y = *reinterpret_cast<uint32_t*>(&lb);
}

// ===========================================================================
// prep: split fp32 -> bf16 hi/lo
// ===========================================================================
__global__ __launch_bounds__(256) void splitx_kernel(
    const float4* __restrict__ in, __nv_bfloat162* __restrict__ h,
    __nv_bfloat162* __restrict__ l)
{
    size_t i = (size_t)blockIdx.x * 256 + threadIdx.x;
    float4 v = in[i];
    float f[4] = {v.x, v.y, v.z, v.w};
    uint2 hp, lp;
    split4_pack(f, hp, lp);
    *reinterpret_cast<uint2*>(h + 2 * i) = hp;
    *reinterpret_cast<uint2*>(l + 2 * i) = lp;
}

// ===========================================================================
// prep: W[K,N] fp32 -> Wt[N,K] bf16 hi/lo, 4 mats in one launch (blockIdx.z).
// Wq (mat 0) pre-scaled by 0.125 (exact power of 2; commutes with rounding).
// ===========================================================================
__global__ __launch_bounds__(256) void wtrans_kernel(
    const float* __restrict__ W0, const float* __restrict__ W1,
    const float* __restrict__ W2, const float* __restrict__ W3,
    __nv_bfloat16* __restrict__ th, __nv_bfloat16* __restrict__ tl)
{
    __shared__ float tile[32][33];
    const int mat = blockIdx.z;
    const float* W = (mat == 0) ? W0 : (mat == 1) ? W1 : (mat == 2) ? W2 : W3;
    const float scale = (mat == 0) ? 0.125f : 1.0f;
    __nv_bfloat16* thm = th + (size_t)mat * DM * DM;
    __nv_bfloat16* tlm = tl + (size_t)mat * DM * DM;

    const int n0 = blockIdx.x * 32, k0 = blockIdx.y * 32;
    const int tx = threadIdx.x, ty = threadIdx.y;
    for (int r = ty; r < 32; r += 8)
        tile[r][tx] = W[(size_t)(k0 + r) * DM + n0 + tx];
    __syncthreads();
    for (int r = ty; r < 32; r += 8) {
        float v = tile[tx][r] * scale;
        __nv_bfloat16 h, l;
        split1(v, h, l);
        size_t o = (size_t)(n0 + r) * DM + k0 + tx;
        thm[o] = h;
        tlm[o] = l;
    }
}

// ---------------- shared GEMM mainloop (macro-free duplication) ----------
#define BKC 64
#define NCH2 (DM / BKC) // 16
#define SSTRIDE 72
#define GEMM_SMEM ((64 + 64 + 256 + 256) * SSTRIDE * 2) // 92160 B
#define CS_STRIDE 264 // fp32 epilogue staging stride (64x264x4 = 67584 B)

// ===========================================================================
// GEMM variant A: fp32 output (O-projection). R14/R15/R16 mainloop exactly.
// ===========================================================================
__global__ __launch_bounds__(256, 2) void gemm_tc(
    const __nv_bfloat16* __restrict__ Ahg, const __nv_bfloat16* __restrict__ Alg,
    const __nv_bfloat16* __restrict__ Whg, const __nv_bfloat16* __restrict__ Wlg,
    float* __restrict__ C)
{
    extern __shared__ char smem[];
    __nv_bfloat16* As_h = reinterpret_cast<__nv_bfloat16*>(smem);
    __nv_bfloat16* As_l = As_h + 64 * SSTRIDE;
    __nv_bfloat16* Bs_h = As_l + 64 * SSTRIDE;
    __nv_bfloat16* Bs_l = Bs_h + 256 * SSTRIDE;

    const int tid = threadIdx.x;
    const int wid = tid >> 5;
    const int wm = wid >> 2;
    const int wn = wid & 3;
    const int bn = blockIdx.x * 256;
    const int bm = blockIdx.y * 64;

    const __nv_bfloat16* pAh = Ahg + (size_t)bm * DM;
    const __nv_bfloat16* pAl = Alg + (size_t)bm * DM;
    const __nv_bfloat16* pBh = Whg + (size_t)bn * DM;
    const __nv_bfloat16* pBl = Wlg + (size_t)bn * DM;

    wmma::fragment<wmma::accumulator, 16, 16, 16, float> acc[2][4];
#pragma unroll
    for (int i = 0; i < 2; i++)
#pragma unroll
        for (int j = 0; j < 4; j++)
            wmma::fill_fragment(acc[i][j], 0.0f);

#pragma unroll 1
    for (int c = 0; c < NCH2; c++) {
        const int kc = c * BKC;
#pragma unroll
        for (int p = 0; p < 20; p++) {
            const __nv_bfloat16* src;
            __nv_bfloat16* dst;
            int local;
            if (p < 2)       { src = pAh; dst = As_h; local = p * 256 + tid; }
            else if (p < 4)  { src = pAl; dst = As_l; local = (p - 2) * 256 + tid; }
            else if (p < 12) { src = pBh; dst = Bs_h; local = (p - 4) * 256 + tid; }
            else             { src = pBl; dst = Bs_l; local = (p - 12) * 256 + tid; }
            const int row = local >> 3, u = local & 7;
            uint4 val = *reinterpret_cast<const uint4*>(
                src + (size_t)row * DM + kc + u * 8);
            *reinterpret_cast<uint4*>(dst + row * SSTRIDE + u * 8) = val;
        }
        __syncthreads();

#pragma unroll
        for (int ks = 0; ks < 4; ks++) {
            wmma::fragment<wmma::matrix_a, 16, 16, 16, __nv_bfloat16, wmma::row_major> ah[2];
            wmma::fragment<wmma::matrix_b, 16, 16, 16, __nv_bfloat16, wmma::col_major> bh[4];
#pragma unroll
            for (int i = 0; i < 2; i++)
                wmma::load_matrix_sync(ah[i], As_h + (wm * 32 + i * 16) * SSTRIDE + ks * 16, SSTRIDE);
#pragma unroll
            for (int j = 0; j < 4; j++)
                wmma::load_matrix_sync(bh[j], Bs_h + (wn * 64 + j * 16) * SSTRIDE + ks * 16, SSTRIDE);
#pragma unroll
            for (int i = 0; i < 2; i++)
#pragma unroll
                for (int j = 0; j < 4; j++)
                    wmma::mma_sync(acc[i][j], ah[i], bh[j], acc[i][j]);
            {
                wmma::fragment<wmma::matrix_a, 16, 16, 16, __nv_bfloat16, wmma::row_major> al[2];
#pragma unroll
                for (int i = 0; i < 2; i++)
                    wmma::load_matrix_sync(al[i], As_l + (wm * 32 + i * 16) * SSTRIDE + ks * 16, SSTRIDE);
#pragma unroll
                for (int i = 0; i < 2; i++)
#pragma unroll
                    for (int j = 0; j < 4; j++)
                        wmma::mma_sync(acc[i][j], al[i], bh[j], acc[i][j]);
            }
            {
                wmma::fragment<wmma::matrix_b, 16, 16, 16, __nv_bfloat16, wmma::col_major> bl[4];
#pragma unroll
                for (int j = 0; j < 4; j++)
                    wmma::load_matrix_sync(bl[j], Bs_l + (wn * 64 + j * 16) * SSTRIDE + ks * 16, SSTRIDE);
#pragma unroll
                for (int i = 0; i < 2; i++)
#pragma unroll
                    for (int j = 0; j < 4; j++)
                        wmma::mma_sync(acc[i][j], ah[i], bl[j], acc[i][j]);
            }
        }
        __syncthreads();
    }

#pragma unroll
    for (int i = 0; i < 2; i++)
#pragma unroll
        for (int j = 0; j < 4; j++)
            wmma::store_matrix_sync(
                C + (size_t)(bm + wm * 32 + i * 16) * DM + bn + wn * 64 + j * 16,
                acc[i][j], DM, wmma::mem_row_major);
}

// ===========================================================================
// GEMM variant B: bf16 hi/lo split output (fused QKV). Same mainloop;
// epilogue stages acc through smem, splits, writes packed uint2 pairs.
// mat = blockIdx.x >> 2 selects {Q,K,V} weight block and output pair.
// ===========================================================================
__global__ __launch_bounds__(256, 2) void gemm_tc_qkv(
    const __nv_bfloat16* __restrict__ Ahg, const __nv_bfloat16* __restrict__ Alg,
    const __nv_bfloat16* __restrict__ Whg, const __nv_bfloat16* __restrict__ Wlg,
    __nv_bfloat16* __restrict__ Qhg, __nv_bfloat16* __restrict__ Qlg,
    __nv_bfloat16* __restrict__ Khg, __nv_bfloat16* __restrict__ Klg,
    __nv_bfloat16* __restrict__ Vhg, __nv_bfloat16* __restrict__ Vlg)
{
    extern __shared__ char smem[];
    __nv_bfloat16* As_h = reinterpret_cast<__nv_bfloat16*>(smem);
    __nv_bfloat16* As_l = As_h + 64 * SSTRIDE;
    __nv_bfloat16* Bs_h = As_l + 64 * SSTRIDE;
    __nv_bfloat16* Bs_l = Bs_h + 256 * SSTRIDE;

    const int tid = threadIdx.x;
    const int wid = tid >> 5;
    const int wm = wid >> 2;
    const int wn = wid & 3;
    const int mat = blockIdx.x >> 2;
    const int bn = (blockIdx.x & 3) * 256;
    const int bm = blockIdx.y * 64;

    __nv_bfloat16* Chg = (mat == 0) ? Qhg : (mat == 1) ? Khg : Vhg;
    __nv_bfloat16* Clg = (mat == 0) ? Qlg : (mat == 1) ? Klg : Vlg;

    const __nv_bfloat16* pAh = Ahg + (size_t)bm * DM;
    const __nv_bfloat16* pAl = Alg + (size_t)bm * DM;
    const __nv_bfloat16* pBh = Whg + (size_t)mat * DM * DM + (size_t)bn * DM;
    const __nv_bfloat16* pBl = Wlg + (size_t)mat * DM * DM + (size_t)bn * DM;

    wmma::fragment<wmma::accumulator, 16, 16, 16, float> acc[2][4];
#pragma unroll
    for (int i = 0; i < 2; i++)
#pragma unroll
        for (int j = 0; j < 4; j++)
            wmma::fill_fragment(acc[i][j], 0.0f);

#pragma unroll 1
    for (int c = 0; c < NCH2; c++) {
        const int kc = c * BKC;
#pragma unroll
        for (int p = 0; p < 20; p++) {
            const __nv_bfloat16* src;
            __nv_bfloat16* dst;
            int local;
            if (p < 2)       { src = pAh; dst = As_h; local = p * 256 + tid; }
            else if (p < 4)  { src = pAl; dst = As_l; local = (p - 2) * 256 + tid; }
            else if (p < 12) { src = pBh; dst = Bs_h; local = (p - 4) * 256 + tid; }
            else             { src = pBl; dst = Bs_l; local = (p - 12) * 256 + tid; }
            const int row = local >> 3, u = local & 7;
            uint4 val = *reinterpret_cast<const uint4*>(
                src + (size_t)row * DM + kc + u * 8);
            *reinterpret_cast<uint4*>(dst + row * SSTRIDE + u * 8) = val;
        }
        __syncthreads();

#pragma unroll
        for (int ks = 0; ks < 4; ks++) {
            wmma::fragment<wmma::matrix_a, 16, 16, 16, __nv_bfloat16, wmma::row_major> ah[2];
            wmma::fragment<wmma::matrix_b, 16, 16, 16, __nv_bfloat16, wmma::col_major> bh[4];
#pragma unroll
            for (int i = 0; i < 2; i++)
                wmma::load_matrix_sync(ah[i], As_h + (wm * 32 + i * 16) * SSTRIDE + ks * 16, SSTRIDE);
#pragma unroll
            for (int j = 0; j < 4; j++)
                wmma::load_matrix_sync(bh[j], Bs_h + (wn * 64 + j * 16) * SSTRIDE + ks * 16, SSTRIDE);
#pragma unroll
            for (int i = 0; i < 2; i++)
#pragma unroll
                for (int j = 0; j < 4; j++)
                    wmma::mma_sync(acc[i][j], ah[i], bh[j], acc[i][j]);
            {
                wmma::fragment<wmma::matrix_a, 16, 16, 16, __nv_bfloat16, wmma::row_major> al[2];
#pragma unroll
                for (int i = 0; i < 2; i++)
                    wmma::load_matrix_sync(al[i], As_l + (wm * 32 + i * 16) * SSTRIDE + ks * 16, SSTRIDE);
#pragma unroll
                for (int i = 0; i < 2; i++)
#pragma unroll
                    for (int j = 0; j < 4; j++)
                        wmma::mma_sync(acc[i][j], al[i], bh[j], acc[i][j]);
            }
            {
                wmma::fragment<wmma::matrix_b, 16, 16, 16, __nv_bfloat16, wmma::col_major> bl[4];
#pragma unroll
                for (int j = 0; j < 4; j++)
                    wmma::load_matrix_sync(bl[j], Bs_l + (wn * 64 + j * 16) * SSTRIDE + ks * 16, SSTRIDE);
#pragma unroll
                for (int i = 0; i < 2; i++)
#pragma unroll
                    for (int j = 0; j < 4; j++)
                        wmma::mma_sync(acc[i][j], ah[i], bl[j], acc[i][j]);
            }
        }
        __syncthreads();
    }

    // ---- epilogue: acc -> smem fp32 -> split -> packed bf16 pairs ----
    float* Cs = reinterpret_cast<float*>(smem); // 64 x CS_STRIDE
#pragma unroll
    for (int i = 0; i < 2; i++)
#pragma unroll
        for (int j = 0; j < 4; j++)
            wmma::store_matrix_sync(
                Cs + (wm * 32 + i * 16) * CS_STRIDE + wn * 64 + j * 16,
                acc[i][j], CS_STRIDE, wmma::mem_row_major);
    __syncthreads();

    {
        const int row = tid >> 2;       // 0..63
        const int cb = (tid & 3) * 64;  // 0..192
        size_t gofs = (size_t)(bm + row) * DM + bn + cb;
#pragma unroll
        for (int t = 0; t < 16; t++) {
            float f[4];
#pragma unroll
            for (int u = 0; u < 4; u++)
                f[u] = Cs[row * CS_STRIDE + cb + t * 4 + u];
            uint2 hp, lp;
            split4_pack(f, hp, lp);
            *reinterpret_cast<uint2*>(Chg + gofs + t * 4) = hp;
            *reinterpret_cast<uint2*>(Clg + gofs + t * 4) = lp;
        }
    }
}

// ===========================================================================
// Chunked local attention on tensor cores. R17: inputs are pre-split bf16
// hi/lo (Q pre-scaled via Wq) -> staging is pure uint4 copies, no split math.
// ===========================================================================
#define AT_STRIDE 72   // bf16
#define SS_STRIDE 132  // fp32
#define P_STRIDE 136   // bf16
#define O_STRIDE 68    // fp32

#define QH_OFF 0
#define QL_OFF (64 * AT_STRIDE * 2)
#define KH_OFF (2 * 64 * AT_STRIDE * 2)
#define KL_OFF (KH_OFF + 128 * AT_STRIDE * 2)
#define VH_OFF (KL_OFF + 128 * AT_STRIDE * 2)
#define VL_OFF (VH_OFF + 128 * AT_STRIDE * 2)
#define ATTN_SMEM_BYTES (VL_OFF + 128 * AT_STRIDE * 2) // 92160
#define PH_OFF 0
#define PL_OFF (64 * P_STRIDE * 2)

__global__ __launch_bounds__(256, 2) void attn_kernel(
    const __nv_bfloat16* __restrict__ qh, const __nv_bfloat16* __restrict__ ql,
    const __nv_bfloat16* __restrict__ kh, const __nv_bfloat16* __restrict__ kl,
    const __nv_bfloat16* __restrict__ vh, const __nv_bfloat16* __restrict__ vl,
    __nv_bfloat16* __restrict__ oh, __nv_bfloat16* __restrict__ ol)
{
    extern __shared__ char sm[];
    __nv_bfloat16* Qh = reinterpret_cast<__nv_bfloat16*>(sm + QH_OFF);
    __nv_bfloat16* Ql = reinterpret_cast<__nv_bfloat16*>(sm + QL_OFF);
    __nv_bfloat16* Kh = reinterpret_cast<__nv_bfloat16*>(sm + KH_OFF);
    __nv_bfloat16* Kl = reinterpret_cast<__nv_bfloat16*>(sm + KL_OFF);
    __nv_bfloat16* Vh = reinterpret_cast<__nv_bfloat16*>(sm + VH_OFF);
    __nv_bfloat16* Vl = reinterpret_cast<__nv_bfloat16*>(sm + VL_OFF);
    float* Ss = reinterpret_cast<float*>(sm);
    __nv_bfloat16* Ph = reinterpret_cast<__nv_bfloat16*>(sm + PH_OFF);
    __nv_bfloat16* Pl = reinterpret_cast<__nv_bfloat16*>(sm + PL_OFF);
    float* Os = reinterpret_cast<float*>(sm);

    const int bid = blockIdx.x;
    const int rtile = bid & 3;
    const int head = (bid >> 2) & 15;
    const int chunk = (bid >> 6) & (NCHUNK - 1);
    const int b = bid >> 11;

    const int tid = threadIdx.x;
    const int wid = tid >> 5;
    const int wm = wid >> 2;
    const int wn = wid & 3;
    const int c0 = rtile * 64 - 64;
    const size_t base = ((size_t)(b * SEQ + chunk * 256)) * DM + head * HD;

    // ---- stage Q: pure uint4 copies (8 bf16 each) ----
    for (int idx = tid; idx < 64 * 8; idx += 256) {
        int row = idx >> 3;
        int u = idx & 7;
        size_t g = base + (size_t)(rtile * 64 + row) * DM + u * 8;
        *reinterpret_cast<uint4*>(Qh + row * AT_STRIDE + u * 8) =
            *reinterpret_cast<const uint4*>(qh + g);
        *reinterpret_cast<uint4*>(Ql + row * AT_STRIDE + u * 8) =
            *reinterpret_cast<const uint4*>(ql + g);
    }
    // ---- stage K, V: uint4 copies, zero-fill out-of-chunk rows ----
    for (int idx = tid; idx < 128 * 8; idx += 256) {
        int row = idx >> 3;
        int u = idx & 7;
        int jc = c0 + row;
        uint4 khv = make_uint4(0u, 0u, 0u, 0u), klv = khv, vhv = khv, vlv = khv;
        if (jc >= 0) {
            size_t g = base + (size_t)jc * DM + u * 8;
            khv = *reinterpret_cast<const uint4*>(kh + g);
            klv = *reinterpret_cast<const uint4*>(kl + g);
            vhv = *reinterpret_cast<const uint4*>(vh + g);
            vlv = *reinterpret_cast<const uint4*>(vl + g);
        }
        *reinterpret_cast<uint4*>(Kh + row * AT_STRIDE + u * 8) = khv;
        *reinterpret_cast<uint4*>(Kl + row * AT_STRIDE + u * 8) = klv;
        *reinterpret_cast<uint4*>(Vh + row * AT_STRIDE + u * 8) = vhv;
        *reinterpret_cast<uint4*>(Vl + row * AT_STRIDE + u * 8) = vlv;
    }
    __syncthreads();

    // ---- S = (Q/8) @ K^T ----
    wmma::fragment<wmma::accumulator, 16, 16, 16, float> sacc[2][2];
#pragma unroll
    for (int i = 0; i < 2; i++)
#pragma unroll
        for (int j = 0; j < 2; j++)
            wmma::fill_fragment(sacc[i][j], 0.0f);

#pragma unroll
    for (int ks = 0; ks < 4; ks++) {
        wmma::fragment<wmma::matrix_a, 16, 16, 16, __nv_bfloat16, wmma::row_major> ah[2];
        wmma::fragment<wmma::matrix_b, 16, 16, 16, __nv_bfloat16, wmma::col_major> bh[2];
#pragma unroll
        for (int i = 0; i < 2; i++)
            wmma::load_matrix_sync(ah[i], Qh + (wm * 32 + i * 16) * AT_STRIDE + ks * 16, AT_STRIDE);
#pragma unroll
        for (int j = 0; j < 2; j++)
            wmma::load_matrix_sync(bh[j], Kh + (wn * 32 + j * 16) * AT_STRIDE + ks * 16, AT_STRIDE);
#pragma unroll
        for (int i = 0; i < 2; i++)
#pragma unroll
            for (int j = 0; j < 2; j++)
                wmma::mma_sync(sacc[i][j], ah[i], bh[j], sacc[i][j]);
        {
            wmma::fragment<wmma::matrix_a, 16, 16, 16, __nv_bfloat16, wmma::row_major> al[2];
#pragma unroll
            for (int i = 0; i < 2; i++)
                wmma::load_matrix_sync(al[i], Ql + (wm * 32 + i * 16) * AT_STRIDE + ks * 16, AT_STRIDE);
#pragma unroll
            for (int i = 0; i < 2; i++)
#pragma unroll
                for (int j = 0; j < 2; j++)
                    wmma::mma_sync(sacc[i][j], al[i], bh[j], sacc[i][j]);
        }
        {
            wmma::fragment<wmma::matrix_b, 16, 16, 16, __nv_bfloat16, wmma::col_major> bl[2];
#pragma unroll
            for (int j = 0; j < 2; j++)
                wmma::load_matrix_sync(bl[j], Kl + (wn * 32 + j * 16) * AT_STRIDE + ks * 16, AT_STRIDE);
#pragma unroll
            for (int i = 0; i < 2; i++)
#pragma unroll
                for (int j = 0; j < 2; j++)
                    wmma::mma_sync(sacc[i][j], ah[i], bl[j], sacc[i][j]);
        }
    }
    __syncthreads(); // Q/K reads done -> overlay Ss

#pragma unroll
    for (int i = 0; i < 2; i++)
#pragma unroll
        for (int j = 0; j < 2; j++)
            wmma::store_matrix_sync(
                Ss + (wm * 32 + i * 16) * SS_STRIDE + wn * 32 + j * 16,
                sacc[i][j], SS_STRIDE, wmma::mem_row_major);
    __syncthreads();

    // ---- fused masked softmax + P split ----
    {
        const int i = tid >> 2;
        const int sub = tid & 3;
        const int lo = (rtile == 0) ? 64 : i;
        const int hi = i + 64;
        const int jbase = sub * 32;

        float pr[32];
#pragma unroll
        for (int jj = 0; jj < 32; jj++) pr[jj] = Ss[i * SS_STRIDE + jbase + jj];

        float m = -1e30f;
#pragma unroll
        for (int jj = 0; jj < 32; jj++) {
            int j = jbase + jj;
            if (j >= lo && j <= hi) m = fmaxf(m, pr[jj]);
        }
        m = fmaxf(m, __shfl_xor_sync(0xffffffffu, m, 1));
        m = fmaxf(m, __shfl_xor_sync(0xffffffffu, m, 2));

        float s = 0.f;
#pragma unroll
        for (int jj = 0; jj < 32; jj++) {
            int j = jbase + jj;
            float e = 0.f;
            if (j >= lo && j <= hi) {
                e = __expf(pr[jj] - m);
                s += e;
            }
            pr[jj] = e;
        }
        s += __shfl_xor_sync(0xffffffffu, s, 1);
        s += __shfl_xor_sync(0xffffffffu, s, 2);
        float inv = 1.0f / s;

        __syncthreads(); // Ss reads complete -> overlay Ph/Pl

#pragma unroll
        for (int t4 = 0; t4 < 8; t4++) {
            float f[4] = {pr[t4 * 4 + 0] * inv, pr[t4 * 4 + 1] * inv,
                          pr[t4 * 4 + 2] * inv, pr[t4 * 4 + 3] * inv};
            uint2 hp, lp;
            split4_pack(f, hp, lp);
            *reinterpret_cast<uint2*>(Ph + i * P_STRIDE + jbase + t4 * 4) = hp;
            *reinterpret_cast<uint2*>(Pl + i * P_STRIDE + jbase + t4 * 4) = lp;
        }
    }
    __syncthreads();

    // ---- O = P @ V (ph*vh + ph*vl + pl*vh) ----
    wmma::fragment<wmma::accumulator, 16, 16, 16, float> oacc[2];
#pragma unroll
    for (int i = 0; i < 2; i++) wmma::fill_fragment(oacc[i], 0.0f);

#pragma unroll
    for (int ks = 0; ks < 8; ks++) {
        wmma::fragment<wmma::matrix_a, 16, 16, 16, __nv_bfloat16, wmma::row_major> pah[2];
        wmma::fragment<wmma::matrix_b, 16, 16, 16, __nv_bfloat16, wmma::row_major> vbh;
#pragma unroll
        for (int i = 0; i < 2; i++)
            wmma::load_matrix_sync(pah[i], Ph + (wm * 32 + i * 16) * P_STRIDE + ks * 16, P_STRIDE);
        wmma::load_matrix_sync(vbh, Vh + (ks * 16) * AT_STRIDE + wn * 16, AT_STRIDE);
#pragma unroll
        for (int i = 0; i < 2; i++)
            wmma::mma_sync(oacc[i], pah[i], vbh, oacc[i]);
        {
            wmma::fragment<wmma::matrix_b, 16, 16, 16, __nv_bfloat16, wmma::row_major> vbl;
            wmma::load_matrix_sync(vbl, Vl + (ks * 16) * AT_STRIDE + wn * 16, AT_STRIDE);
#pragma unroll
            for (int i = 0; i < 2; i++)
                wmma::mma_sync(oacc[i], pah[i], vbl, oacc[i]);
        }
        {
            wmma::fragment<wmma::matrix_a, 16, 16, 16, __nv_bfloat16, wmma::row_major> pal[2];
#pragma unroll
            for (int i = 0; i < 2; i++)
                wmma::load_matrix_sync(pal[i], Pl + (wm * 32 + i * 16) * P_STRIDE + ks * 16, P_STRIDE);
            wmma::fragment<wmma::matrix_b, 16, 16, 16, __nv_bfloat16, wmma::row_major> vbh2;
            wmma::load_matrix_sync(vbh2, Vh + (ks * 16) * AT_STRIDE + wn * 16, AT_STRIDE);
#pragma unroll
            for (int i = 0; i < 2; i++)
                wmma::mma_sync(oacc[i], pal[i], vbh2, oacc[i]);
        }
    }
    __syncthreads(); // P/V reads done -> overlay Os

#pragma unroll
    for (int i = 0; i < 2; i++)
        wmma::store_matrix_sync(Os + (wm * 32 + i * 16) * O_STRIDE + wn * 16,
                                oacc[i], O_STRIDE, wmma::mem_row_major);
    __syncthreads();

    // ---- packed writeout: split O to bf16 hi/lo ----
    {
        const int row = tid >> 2;
        const int d0 = (tid & 3) * 16;
        size_t off = base + (size_t)(rtile * 64 + row) * DM + d0;
#pragma unroll
        for (int d4 = 0; d4 < 4; d4++) {
            float f[4];
#pragma unroll
            for (int t = 0; t < 4; t++)
                f[t] = Os[row * O_STRIDE + d0 + d4 * 4 + t];
            uint2 hp, lp;
            split4_pack(f, hp, lp);
            *reinterpret_cast<uint2*>(oh + off + d4 * 4) = hp;
            *reinterpret_cast<uint2*>(ol + off + d4 * 4) = lp;
        }
    }
}

// ===========================================================================
// kernel_launch
// ===========================================================================
extern "C" void kernel_launch(void* const* d_in, const int* in_sizes, int n_in,
                              void* d_out, int out_size)
{
    (void)in_sizes; (void)n_in; (void)out_size;
    const float* x  = (const float*)d_in[0];
    const float* Wq = (const float*)d_in[1];
    const float* Wk = (const float*)d_in[2];
    const float* Wv = (const float*)d_in[3];
    const float* Wo = (const float*)d_in[4];
    float* out = (float*)d_out;

    __nv_bfloat16 *qh, *ql, *kh, *kl, *vh, *vl, *ah, *al, *wh, *wl;
    cudaGetSymbolAddress((void**)&qh, g_qh);
    cudaGetSymbolAddress((void**)&ql, g_ql);
    cudaGetSymbolAddress((void**)&kh, g_kh);
    cudaGetSymbolAddress((void**)&kl, g_kl);
    cudaGetSymbolAddress((void**)&vh, g_vh);
    cudaGetSymbolAddress((void**)&vl, g_vl);
    cudaGetSymbolAddress((void**)&ah, g_ah);
    cudaGetSymbolAddress((void**)&al, g_al);
    cudaGetSymbolAddress((void**)&wh, g_wh);
    cudaGetSymbolAddress((void**)&wl, g_wl);

    cudaFuncSetAttribute(gemm_tc, cudaFuncAttributeMaxDynamicSharedMemorySize,
                         GEMM_SMEM);
    cudaFuncSetAttribute(gemm_tc_qkv, cudaFuncAttributeMaxDynamicSharedMemorySize,
                         GEMM_SMEM);
    cudaFuncSetAttribute(attn_kernel, cudaFuncAttributeMaxDynamicSharedMemorySize,
                         ATTN_SMEM_BYTES);

    // 1) split x into bf16 hi/lo
    splitx_kernel<<<(MTOT * DM / 4) / 256, 256>>>(
        (const float4*)x, (__nv_bfloat162*)ah, (__nv_bfloat162*)al);

    // 2) transpose+split all four weights (one launch; Wq pre-scaled 1/8)
    dim3 wgrid(DM / 32, DM / 32, 4);
    dim3 wblk(32, 8);
    wtrans_kernel<<<wgrid, wblk>>>(Wq, Wk, Wv, Wo, wh, wl);

    // 3) fused Q/K/V projection -> bf16 hi/lo outputs
    dim3 qkvgrid(12, MTOT / 64); // (12, 512)
    gemm_tc_qkv<<<qkvgrid, 256, GEMM_SMEM>>>(ah, al, wh, wl,
                                             qh, ql, kh, kl, vh, vl);

    // 4) attention on tensor cores (bf16 split inputs; writes ah/al)
    attn_kernel<<<BATCH * NCHUNK * NH * 4, 256, ATTN_SMEM_BYTES>>>(
        qh, ql, kh, kl, vh, vl, ah, al);

    // 5) output projection (fp32 out)
    dim3 ogrid(4, MTOT / 64);
    gemm_tc<<<ogrid, 256, GEMM_SMEM>>>(ah, al, wh + 3 * (size_t)DM * DM,
                                       wl + 3 * (size_t)DM * DM, out);
}